// round 12
// baseline (speedup 1.0000x reference)
#include <cuda_runtime.h>
#include <cuda_fp16.h>
#include <cstdint>
#include <math.h>

#define BATCH 4096
#define T 96
#define C 256
#define H 64
#define SCALE 0.0625f
#define NT 256

// element strides (fp16)
#define XS 72
#define WS 72
#define KS 72
#define PS 104
#define X32S 68     // fp32 staging stride (floats)

// region A (phase 1), byte offsets
#define XH_OFF 0              // 13824
#define WB_OFF 13824          // 3 W blocks (hi only), 9216 each -> ends 41472
#define WBLK   9216
#define X32_OFF 41472         // 2 bufs x 96*68*4 = 2*26112 -> ends 93696
#define X32B   26112
// region B (kqv, overlays region A after phase 1)
#define KH_OFF 0
#define QH_OFF 13824
#define QL_OFF 27648
#define VH_OFF 41472          // ends 55296 (X32 dead by then)
// region C (P hi/lo, overlays k/q after S consumed; v stays live)
#define PH_OFF 0
#define PL_OFF 19968          // ends 39936
// softmax scratch
#define SMAX_OFF 55296        // [96][9] floats
#define RMAX_OFF 58752        // [96]
#define INV_OFF  59136        // [96]
#define SMEM_BYTES 93696

// -------- W pre-converted to fp16 (shared across all CTAs) --------
__device__ __half g_Wh[3][C * H];

__global__ void convW_kernel(const float* __restrict__ Wk,
                             const float* __restrict__ Wq,
                             const float* __restrict__ Wv)
{
    int idx = blockIdx.x * 256 + threadIdx.x;
    int wm  = idx >> 14;
    int r   = idx & 16383;
    const float* W = (wm == 0) ? Wk : (wm == 1 ? Wq : Wv);
    g_Wh[wm][r] = __float2half_rn(W[r]);
}

__device__ __forceinline__ uint32_t smem_u32(const void* p) {
    uint32_t a;
    asm("{ .reg .u64 t; cvta.to.shared.u64 t, %1; cvt.u32.u64 %0, t; }" : "=r"(a) : "l"(p));
    return a;
}
__device__ __forceinline__ void ldsm_x4(unsigned* r, uint32_t addr) {
    asm volatile("ldmatrix.sync.aligned.m8n8.x4.shared.b16 {%0,%1,%2,%3}, [%4];"
                 : "=r"(r[0]), "=r"(r[1]), "=r"(r[2]), "=r"(r[3]) : "r"(addr));
}
__device__ __forceinline__ void ldsm_x4t(unsigned* r, uint32_t addr) {
    asm volatile("ldmatrix.sync.aligned.m8n8.x4.trans.shared.b16 {%0,%1,%2,%3}, [%4];"
                 : "=r"(r[0]), "=r"(r[1]), "=r"(r[2]), "=r"(r[3]) : "r"(addr));
}
__device__ __forceinline__ void mma16816(float* d, const unsigned* a, const unsigned* b) {
    asm volatile("mma.sync.aligned.m16n8k16.row.col.f32.f16.f16.f32 "
                 "{%0,%1,%2,%3}, {%4,%5,%6,%7}, {%8,%9}, {%0,%1,%2,%3};"
                 : "+f"(d[0]), "+f"(d[1]), "+f"(d[2]), "+f"(d[3])
                 : "r"(a[0]), "r"(a[1]), "r"(a[2]), "r"(a[3]), "r"(b[0]), "r"(b[1]));
}
__device__ __forceinline__ void split(float f, uint16_t& h, uint16_t& l) {
    __half hh = __float2half_rn(f);
    h = __half_as_ushort(hh);
    l = __half_as_ushort(__float2half_rn(f - __half2float(hh)));
}
__device__ __forceinline__ uint32_t pack2h(float a, float b) {
    return (uint32_t)__half_as_ushort(__float2half_rn(a))
         | ((uint32_t)__half_as_ushort(__float2half_rn(b)) << 16);
}
__device__ __forceinline__ void cp16(uint32_t dst, const void* src) {
    asm volatile("cp.async.cg.shared.global [%0], [%1], 16;"
                 :: "r"(dst), "l"(__cvta_generic_to_global(src)) : "memory");
}
#define CP_COMMIT() asm volatile("cp.async.commit_group;" ::: "memory")
#define CP_WAIT0()  asm volatile("cp.async.wait_group 0;" ::: "memory")

__global__ __launch_bounds__(NT, 2)
void head_attn_v9(const float* __restrict__ x,
                  float* __restrict__ out)
{
    extern __shared__ char smem[];
    const uint32_t sb = smem_u32(smem);
    const int tid  = threadIdx.x;
    const int w    = tid >> 5;
    const int lane = tid & 31;
    const int b    = blockIdx.x;
    const float* xb = x + (size_t)b * T * C;

#define CP_X(ck, bf) do {                                                          \
    _Pragma("unroll")                                                              \
    for (int i = 0; i < 6; i++) {                                                  \
        int idx = tid + i * NT;                                                    \
        int row = idx >> 4, c4 = idx & 15;                                         \
        cp16(sb + X32_OFF + (bf) * X32B + (uint32_t)(row * X32S + c4 * 4) * 4u,    \
             xb + row * C + (ck) * 64 + c4 * 4);                                   \
    }                                                                              \
} while (0)
#define CP_W(ck) do {                                                              \
    _Pragma("unroll")                                                              \
    for (int i = 0; i < 6; i++) {                                                  \
        int idx = tid + i * NT;                                                    \
        int wm2 = idx >> 9, r = (idx >> 3) & 63, c8 = idx & 7;                     \
        cp16(sb + WB_OFF + wm2 * WBLK + (uint32_t)(r * WS + c8 * 8) * 2u,          \
             g_Wh[wm2] + ((ck) * 64 + r) * H + c8 * 8);                            \
    }                                                                              \
} while (0)

    // prologue: x0, x1, W0 in flight
    CP_X(0, 0); CP_COMMIT();
    CP_X(1, 1); CP_COMMIT();
    CP_W(0);    CP_COMMIT();

    const int mh = w >> 2, q4 = w & 3;
    float acc[3][3][2][4];
#pragma unroll
    for (int j = 0; j < 3; j++)
#pragma unroll
        for (int mi = 0; mi < 3; mi++)
#pragma unroll
            for (int nb = 0; nb < 2; nb++)
#pragma unroll
                for (int i = 0; i < 4; i++) acc[j][mi][nb][i] = 0.f;

    CP_WAIT0();
    __syncthreads();

    // ---------------- phase 1: 4 pipelined K-chunks of 64 ----------------
#pragma unroll 1
    for (int c = 0; c < 4; c++) {
#pragma unroll
        for (int i = 0; i < 6; i++) {
            int idx = tid + i * NT;
            int row = idx >> 4, c4 = idx & 15;
            const float4 v = *(const float4*)(smem + X32_OFF + (c & 1) * X32B
                                              + (uint32_t)(row * X32S + c4 * 4) * 4u);
            *(uint2*)(smem + XH_OFF + (uint32_t)(row * XS + c4 * 4) * 2u) =
                make_uint2(pack2h(v.x, v.y), pack2h(v.z, v.w));
        }
        CP_WAIT0();
        __syncthreads();
        if (c < 2) { CP_X(c + 2, c & 1); CP_COMMIT(); }

#pragma unroll
        for (int kit = 0; kit < 4; kit++) {
            const int k0 = kit * 16;
            unsigned ah[3][4];
#pragma unroll
            for (int mi = 0; mi < 3; mi++) {
                uint32_t ao = (uint32_t)((mh * 48 + mi * 16 + (lane & 15)) * XS
                                         + k0 + 8 * (lane >> 4)) * 2u;
                ldsm_x4(ah[mi], sb + XH_OFF + ao);
            }
#pragma unroll
            for (int j = 0; j < 3; j++) {
                const int p  = q4 * 3 + j;
                const int wm = p >> 2, nq = p & 3;
                uint32_t bo = (uint32_t)((k0 + (lane & 15)) * WS
                                         + nq * 16 + 8 * (lane >> 4)) * 2u;
                unsigned bh[4];
                ldsm_x4t(bh, sb + WB_OFF + wm * WBLK + bo);
#pragma unroll
                for (int mi = 0; mi < 3; mi++)
#pragma unroll
                    for (int nb = 0; nb < 2; nb++)
                        mma16816(acc[j][mi][nb], ah[mi], bh + 2 * nb);
            }
        }
        __syncthreads();
        if (c < 3) { CP_W(c + 1); CP_COMMIT(); }
    }

    // ---------------- spill: q hi/lo, k hi, v hi ----------------
#pragma unroll
    for (int j = 0; j < 3; j++) {
        const int p  = q4 * 3 + j;
        const int wm = p >> 2, nq = p & 3;
        char* hb = smem + (wm == 0 ? KH_OFF : (wm == 1 ? QH_OFF : VH_OFF));
#pragma unroll
        for (int mi = 0; mi < 3; mi++) {
            const int r0 = mh * 48 + mi * 16 + (lane >> 2);
#pragma unroll
            for (int nb = 0; nb < 2; nb++) {
                const int c0 = nq * 16 + nb * 8 + 2 * (lane & 3);
                if (wm == 1) {
                    char* lb = smem + QL_OFF;
                    uint16_t h0, l0, h1, l1;
                    split(acc[j][mi][nb][0], h0, l0); split(acc[j][mi][nb][1], h1, l1);
                    *(uint32_t*)(hb + (r0 * KS + c0) * 2) = (uint32_t)h0 | ((uint32_t)h1 << 16);
                    *(uint32_t*)(lb + (r0 * KS + c0) * 2) = (uint32_t)l0 | ((uint32_t)l1 << 16);
                    split(acc[j][mi][nb][2], h0, l0); split(acc[j][mi][nb][3], h1, l1);
                    *(uint32_t*)(hb + ((r0 + 8) * KS + c0) * 2) = (uint32_t)h0 | ((uint32_t)h1 << 16);
                    *(uint32_t*)(lb + ((r0 + 8) * KS + c0) * 2) = (uint32_t)l0 | ((uint32_t)l1 << 16);
                } else {
                    *(uint32_t*)(hb + (r0 * KS + c0) * 2) =
                        pack2h(acc[j][mi][nb][0], acc[j][mi][nb][1]);
                    *(uint32_t*)(hb + ((r0 + 8) * KS + c0) * 2) =
                        pack2h(acc[j][mi][nb][2], acc[j][mi][nb][3]);
                }
            }
        }
    }
    __syncthreads();

    // ---------------- phase 2: S = q k^T, one mt per warp, q hoisted ----------------
    // w:      0  1  2  3  4  5  6  7
    // mt:     5  5  4  4  3  2  1  0
    // nb0:    0  3  0  3  0  0  0  0
    // cnt:    3  3  3  2  4  3  2  1
    const int mt  = (0x01234455 >> (4 * (7 - w))) & 15;   // {5,5,4,4,3,2,1,0}[w]
    const int nb0 = (w == 1 || w == 3) ? 3 : 0;
    const int cnt = (0x12342333 >> (4 * (7 - w))) & 15;   // wait—encode directly below
    // (use explicit tables to avoid encoding bugs)
    const int MTT[8]  = {5, 5, 4, 4, 3, 2, 1, 0};
    const int NB0T[8] = {0, 3, 0, 3, 0, 0, 0, 0};
    const int CNTT[8] = {3, 3, 3, 2, 4, 3, 2, 1};
    const int mt2  = MTT[w];
    const int nbb  = NB0T[w];
    const int cnt2 = CNTT[w];
    (void)mt; (void)nb0; (void)cnt;

    // hoist q fragments for all 4 k-steps
    unsigned qh[4][4], ql[4][4];
#pragma unroll
    for (int kit = 0; kit < 4; kit++) {
        uint32_t ao = (uint32_t)((mt2 * 16 + (lane & 15)) * KS + kit * 16 + 8 * (lane >> 4)) * 2u;
        ldsm_x4(qh[kit], sb + QH_OFF + ao);
        ldsm_x4(ql[kit], sb + QL_OFF + ao);
    }

    float s[4][2][4];
#pragma unroll
    for (int u = 0; u < 4; u++)
#pragma unroll
        for (int nb = 0; nb < 2; nb++)
#pragma unroll
            for (int i = 0; i < 4; i++) s[u][nb][i] = 0.f;

#pragma unroll
    for (int u = 0; u < 4; u++) {
        if (u >= cnt2) break;
        const int nb2 = nbb + u;
#pragma unroll
        for (int kit = 0; kit < 4; kit++) {
            unsigned kh[4];
            uint32_t bo = (uint32_t)((nb2 * 16 + (lane & 7) + 8 * (lane >> 4)) * KS
                                     + kit * 16 + 8 * ((lane >> 3) & 1)) * 2u;
            ldsm_x4(kh, sb + KH_OFF + bo);
            mma16816(s[u][0], qh[kit], kh);
            mma16816(s[u][0], ql[kit], kh);
            mma16816(s[u][1], qh[kit], kh + 2);
            mma16816(s[u][1], ql[kit], kh + 2);
        }
    }

    // partial row-max per unit -> SMAX[r][nb2]
    {
        float* SMX = (float*)(smem + SMAX_OFF);
        const int r0 = mt2 * 16 + (lane >> 2), r1 = r0 + 8;
#pragma unroll
        for (int u = 0; u < 4; u++) {
            if (u >= cnt2) break;
            const int nb2 = nbb + u;
            const int cbase = nb2 * 16 + 2 * (lane & 3);
            const bool diag = (nb2 == mt2);
            float m0 = -1e30f, m1 = -1e30f;
#pragma unroll
            for (int nb = 0; nb < 2; nb++) {
                int cc = cbase + nb * 8;
                if (!diag || cc     <= r0) m0 = fmaxf(m0, s[u][nb][0]);
                if (!diag || cc + 1 <= r0) m0 = fmaxf(m0, s[u][nb][1]);
                if (!diag || cc     <= r1) m1 = fmaxf(m1, s[u][nb][2]);
                if (!diag || cc + 1 <= r1) m1 = fmaxf(m1, s[u][nb][3]);
            }
            m0 = fmaxf(m0, __shfl_xor_sync(0xffffffffu, m0, 1));
            m0 = fmaxf(m0, __shfl_xor_sync(0xffffffffu, m0, 2));
            m1 = fmaxf(m1, __shfl_xor_sync(0xffffffffu, m1, 1));
            m1 = fmaxf(m1, __shfl_xor_sync(0xffffffffu, m1, 2));
            if ((lane & 3) == 0) {
                SMX[r0 * 9 + nb2] = m0;
                SMX[r1 * 9 + nb2] = m1;
            }
        }
    }
    __syncthreads();

    if (tid < T) {
        const float* SMX = (const float*)(smem + SMAX_OFF);
        float m = SMX[tid * 9];
        const int segs = tid >> 4;
#pragma unroll 1
        for (int sg = 1; sg <= segs; sg++) m = fmaxf(m, SMX[tid * 9 + sg]);
        ((float*)(smem + RMAX_OFF))[tid] = m;
    }
    __syncthreads();

    // exp + P write (unnormalized) + partial sums
    {
        const float* RMX = (const float*)(smem + RMAX_OFF);
        float* SMX = (float*)(smem + SMAX_OFF);
        uint16_t* PH = (uint16_t*)(smem + PH_OFF);
        uint16_t* PL = (uint16_t*)(smem + PL_OFF);
        const int r0 = mt2 * 16 + (lane >> 2), r1 = r0 + 8;
        const float rm0 = RMX[r0] * SCALE, rm1 = RMX[r1] * SCALE;
#pragma unroll
        for (int u = 0; u < 4; u++) {
            if (u >= cnt2) break;
            const int nb2 = nbb + u;
            const int cbase = nb2 * 16 + 2 * (lane & 3);
            const bool diag = (nb2 == mt2);
            float sum0 = 0.f, sum1 = 0.f;
#pragma unroll
            for (int nb = 0; nb < 2; nb++) {
                int cc = cbase + nb * 8;
                float p0 = (!diag || cc     <= r0) ? __expf(s[u][nb][0] * SCALE - rm0) : 0.f;
                float p1 = (!diag || cc + 1 <= r0) ? __expf(s[u][nb][1] * SCALE - rm0) : 0.f;
                float p2 = (!diag || cc     <= r1) ? __expf(s[u][nb][2] * SCALE - rm1) : 0.f;
                float p3 = (!diag || cc + 1 <= r1) ? __expf(s[u][nb][3] * SCALE - rm1) : 0.f;
                sum0 += p0 + p1; sum1 += p2 + p3;
                uint16_t h0, l0, h1, l1;
                split(p0, h0, l0); split(p1, h1, l1);
                *(uint32_t*)&PH[r0 * PS + cc] = (uint32_t)h0 | ((uint32_t)h1 << 16);
                *(uint32_t*)&PL[r0 * PS + cc] = (uint32_t)l0 | ((uint32_t)l1 << 16);
                split(p2, h0, l0); split(p3, h1, l1);
                *(uint32_t*)&PH[r1 * PS + cc] = (uint32_t)h0 | ((uint32_t)h1 << 16);
                *(uint32_t*)&PL[r1 * PS + cc] = (uint32_t)l0 | ((uint32_t)l1 << 16);
            }
            sum0 += __shfl_xor_sync(0xffffffffu, sum0, 1);
            sum0 += __shfl_xor_sync(0xffffffffu, sum0, 2);
            sum1 += __shfl_xor_sync(0xffffffffu, sum1, 1);
            sum1 += __shfl_xor_sync(0xffffffffu, sum1, 2);
            if ((lane & 3) == 0) {
                SMX[r0 * 9 + nb2] = sum0;
                SMX[r1 * 9 + nb2] = sum1;
            }
        }
    }
    __syncthreads();

    if (tid < T) {
        const float* SMX = (const float*)(smem + SMAX_OFF);
        float sm = SMX[tid * 9];
        const int segs = tid >> 4;
#pragma unroll 1
        for (int sg = 1; sg <= segs; sg++) sm += SMX[tid * 9 + sg];
        ((float*)(smem + INV_OFF))[tid] = 1.f / sm;
    }
    __syncthreads();

    // ---------------- phase 3: O = P @ v, balanced (mt, nh) units ----------------
    const uint32_t V0 = 0x547698BAu, V1 = 0x10320000u, CNT3 = 0x22221111u;
    const int n3  = (CNT3 >> (4 * w)) & 15;
    const int vu0 = (V0 >> (4 * w)) & 15;
    const int vu1 = (V1 >> (4 * w)) & 15;
    const float* INV = (const float*)(smem + INV_OFF);
    float* ob = out + (size_t)b * T * H;

    float o[2][4][4];
#pragma unroll
    for (int u = 0; u < 2; u++)
#pragma unroll
        for (int nb = 0; nb < 4; nb++)
#pragma unroll
            for (int i = 0; i < 4; i++) o[u][nb][i] = 0.f;

#pragma unroll
    for (int u = 0; u < 2; u++) {
        if (u >= n3) break;
        const int unit = (u == 0) ? vu0 : vu1;
        const int pmt = unit >> 1, nh = unit & 1;
#pragma unroll 1
        for (int kit = 0; kit <= pmt; kit++) {
            const int k0 = kit * 16;
            unsigned ph[4], pl[4], vh[4];
            uint32_t ao = (uint32_t)((pmt * 16 + (lane & 15)) * PS + k0 + 8 * (lane >> 4)) * 2u;
            ldsm_x4(ph, sb + PH_OFF + ao);
            ldsm_x4(pl, sb + PL_OFF + ao);
            uint32_t bo = (uint32_t)((k0 + (lane & 15)) * KS + nh * 32 + 16 * (lane >> 4)) * 2u;
            ldsm_x4t(vh, sb + VH_OFF + bo);
            mma16816(o[u][0], ph, vh);
            mma16816(o[u][0], pl, vh);
            mma16816(o[u][2], ph, vh + 2);
            mma16816(o[u][2], pl, vh + 2);
            uint32_t bo2 = bo + 16u;
            ldsm_x4t(vh, sb + VH_OFF + bo2);
            mma16816(o[u][1], ph, vh);
            mma16816(o[u][1], pl, vh);
            mma16816(o[u][3], ph, vh + 2);
            mma16816(o[u][3], pl, vh + 2);
        }
        const int r0 = pmt * 16 + (lane >> 2), r1 = r0 + 8;
        const float inv0 = INV[r0], inv1 = INV[r1];
#pragma unroll
        for (int nb = 0; nb < 4; nb++) {
            int cc = nh * 32 + nb * 8 + 2 * (lane & 3);
            *(float2*)&ob[r0 * H + cc] = make_float2(o[u][nb][0] * inv0, o[u][nb][1] * inv0);
            *(float2*)&ob[r1 * H + cc] = make_float2(o[u][nb][2] * inv1, o[u][nb][3] * inv1);
        }
    }
}

extern "C" void kernel_launch(void* const* d_in, const int* in_sizes, int n_in,
                              void* d_out, int out_size)
{
    const float* x  = (const float*)d_in[0];
    const float* Wk = (const float*)d_in[1];
    const float* Wq = (const float*)d_in[2];
    const float* Wv = (const float*)d_in[3];
    float* out = (float*)d_out;

    static bool attr_set = false;
    if (!attr_set) {
        cudaFuncSetAttribute(head_attn_v9,
                             cudaFuncAttributeMaxDynamicSharedMemorySize, SMEM_BYTES);
        attr_set = true;
    }
    convW_kernel<<<192, 256>>>(Wk, Wq, Wv);
    head_attn_v9<<<BATCH, NT, SMEM_BYTES>>>(x, out);
}

// round 13
// speedup vs baseline: 1.0590x; 1.0590x over previous
#include <cuda_runtime.h>
#include <cuda_fp16.h>
#include <cstdint>
#include <math.h>

#define BATCH 4096
#define T 96
#define C 256
#define H 64
#define SCALE 0.0625f
#define NT 256

// element strides (fp16)
#define XS 72
#define WS 72
#define KS 72
#define PS 104
#define X32S 68     // fp32 staging stride (floats)

// region A (phase 1), byte offsets
#define XH_OFF 0              // 13824
#define WB_OFF 13824          // TWO W buffers, each 3 x 9216 = 27648 -> ends 69120
#define WBLK   9216
#define WBUF   27648
#define X32_OFF 69120         // single buf 96*68*4 = 26112 -> ends 95232
// region B (kqv, overlays region A after phase 1)
#define KH_OFF 0
#define QH_OFF 13824
#define QL_OFF 27648
#define VH_OFF 41472          // ends 55296
// region C (P hi only, overlays k/q after S consumed; v stays live)
#define PH_OFF 0              // 19968 -> ends 19968
// softmax scratch
#define SMAX_OFF 55296        // [96][9] floats
#define RMAX_OFF 58752        // [96]
#define INV_OFF  59136        // [96]
#define SMEM_BYTES 95232

// -------- W pre-converted to fp16 (shared across all CTAs) --------
__device__ __half g_Wh[3][C * H];

__global__ void convW_kernel(const float* __restrict__ Wk,
                             const float* __restrict__ Wq,
                             const float* __restrict__ Wv)
{
    int idx = blockIdx.x * 256 + threadIdx.x;
    int wm  = idx >> 14;
    int r   = idx & 16383;
    const float* W = (wm == 0) ? Wk : (wm == 1 ? Wq : Wv);
    g_Wh[wm][r] = __float2half_rn(W[r]);
}

__device__ __forceinline__ uint32_t smem_u32(const void* p) {
    uint32_t a;
    asm("{ .reg .u64 t; cvta.to.shared.u64 t, %1; cvt.u32.u64 %0, t; }" : "=r"(a) : "l"(p));
    return a;
}
__device__ __forceinline__ void ldsm_x4(unsigned* r, uint32_t addr) {
    asm volatile("ldmatrix.sync.aligned.m8n8.x4.shared.b16 {%0,%1,%2,%3}, [%4];"
                 : "=r"(r[0]), "=r"(r[1]), "=r"(r[2]), "=r"(r[3]) : "r"(addr));
}
__device__ __forceinline__ void ldsm_x4t(unsigned* r, uint32_t addr) {
    asm volatile("ldmatrix.sync.aligned.m8n8.x4.trans.shared.b16 {%0,%1,%2,%3}, [%4];"
                 : "=r"(r[0]), "=r"(r[1]), "=r"(r[2]), "=r"(r[3]) : "r"(addr));
}
__device__ __forceinline__ void mma16816(float* d, const unsigned* a, const unsigned* b) {
    asm volatile("mma.sync.aligned.m16n8k16.row.col.f32.f16.f16.f32 "
                 "{%0,%1,%2,%3}, {%4,%5,%6,%7}, {%8,%9}, {%0,%1,%2,%3};"
                 : "+f"(d[0]), "+f"(d[1]), "+f"(d[2]), "+f"(d[3])
                 : "r"(a[0]), "r"(a[1]), "r"(a[2]), "r"(a[3]), "r"(b[0]), "r"(b[1]));
}
__device__ __forceinline__ void split(float f, uint16_t& h, uint16_t& l) {
    __half hh = __float2half_rn(f);
    h = __half_as_ushort(hh);
    l = __half_as_ushort(__float2half_rn(f - __half2float(hh)));
}
__device__ __forceinline__ uint32_t pack2h(float a, float b) {
    return (uint32_t)__half_as_ushort(__float2half_rn(a))
         | ((uint32_t)__half_as_ushort(__float2half_rn(b)) << 16);
}
__device__ __forceinline__ void cp16(uint32_t dst, const void* src) {
    asm volatile("cp.async.cg.shared.global [%0], [%1], 16;"
                 :: "r"(dst), "l"(__cvta_generic_to_global(src)) : "memory");
}
#define CP_COMMIT() asm volatile("cp.async.commit_group;" ::: "memory")
#define CP_WAIT0()  asm volatile("cp.async.wait_group 0;" ::: "memory")

__global__ __launch_bounds__(NT, 2)
void head_attn_v10(const float* __restrict__ x,
                   float* __restrict__ out)
{
    extern __shared__ char smem[];
    const uint32_t sb = smem_u32(smem);
    const int tid  = threadIdx.x;
    const int w    = tid >> 5;
    const int lane = tid & 31;
    const int b    = blockIdx.x;
    const float* xb = x + (size_t)b * T * C;

#define CP_X(ck) do {                                                              \
    _Pragma("unroll")                                                              \
    for (int i = 0; i < 6; i++) {                                                  \
        int idx = tid + i * NT;                                                    \
        int row = idx >> 4, c4 = idx & 15;                                         \
        cp16(sb + X32_OFF + (uint32_t)(row * X32S + c4 * 4) * 4u,                  \
             xb + row * C + (ck) * 64 + c4 * 4);                                   \
    }                                                                              \
} while (0)
#define CP_W(ck) do {                                                              \
    _Pragma("unroll")                                                              \
    for (int i = 0; i < 6; i++) {                                                  \
        int idx = tid + i * NT;                                                    \
        int wm2 = idx >> 9, r = (idx >> 3) & 63, c8 = idx & 7;                     \
        cp16(sb + WB_OFF + ((ck) & 1) * WBUF + wm2 * WBLK                          \
                 + (uint32_t)(r * WS + c8 * 8) * 2u,                               \
             g_Wh[wm2] + ((ck) * 64 + r) * H + c8 * 8);                            \
    }                                                                              \
} while (0)

    // prologue: x0 + W0 in flight
    CP_X(0); CP_W(0); CP_COMMIT();

    const int mh = w >> 2, q4 = w & 3;
    float acc[3][3][2][4];
#pragma unroll
    for (int j = 0; j < 3; j++)
#pragma unroll
        for (int mi = 0; mi < 3; mi++)
#pragma unroll
            for (int nb = 0; nb < 2; nb++)
#pragma unroll
                for (int i = 0; i < 4; i++) acc[j][mi][nb][i] = 0.f;

    // ---------------- phase 1: 4 pipelined K-chunks of 64 ----------------
#pragma unroll 1
    for (int c = 0; c < 4; c++) {
        CP_WAIT0();            // x(c), W(c) arrived
        // convert fp32 staging -> fp16 XH (each thread converts what it copied)
#pragma unroll
        for (int i = 0; i < 6; i++) {
            int idx = tid + i * NT;
            int row = idx >> 4, c4 = idx & 15;
            const float4 v = *(const float4*)(smem + X32_OFF
                                              + (uint32_t)(row * X32S + c4 * 4) * 4u);
            *(uint2*)(smem + XH_OFF + (uint32_t)(row * XS + c4 * 4) * 2u) =
                make_uint2(pack2h(v.x, v.y), pack2h(v.z, v.w));
        }
        __syncthreads();       // XH ready, W(c) visible to all, X32 free
        if (c < 3) { CP_X(c + 1); CP_W(c + 1); CP_COMMIT(); }

        const uint32_t wbase = sb + WB_OFF + (uint32_t)(c & 1) * WBUF;
#pragma unroll
        for (int kit = 0; kit < 4; kit++) {
            const int k0 = kit * 16;
            unsigned ah[3][4];
#pragma unroll
            for (int mi = 0; mi < 3; mi++) {
                uint32_t ao = (uint32_t)((mh * 48 + mi * 16 + (lane & 15)) * XS
                                         + k0 + 8 * (lane >> 4)) * 2u;
                ldsm_x4(ah[mi], sb + XH_OFF + ao);
            }
#pragma unroll
            for (int j = 0; j < 3; j++) {
                const int p  = q4 * 3 + j;
                const int wm = p >> 2, nq = p & 3;
                uint32_t bo = (uint32_t)((k0 + (lane & 15)) * WS
                                         + nq * 16 + 8 * (lane >> 4)) * 2u;
                unsigned bh[4];
                ldsm_x4t(bh, wbase + wm * WBLK + bo);
#pragma unroll
                for (int mi = 0; mi < 3; mi++)
#pragma unroll
                    for (int nb = 0; nb < 2; nb++)
                        mma16816(acc[j][mi][nb], ah[mi], bh + 2 * nb);
            }
        }
        __syncthreads();       // XH free for next convert
    }

    // ---------------- spill: q hi/lo, k hi, v hi ----------------
#pragma unroll
    for (int j = 0; j < 3; j++) {
        const int p  = q4 * 3 + j;
        const int wm = p >> 2, nq = p & 3;
        char* hb = smem + (wm == 0 ? KH_OFF : (wm == 1 ? QH_OFF : VH_OFF));
#pragma unroll
        for (int mi = 0; mi < 3; mi++) {
            const int r0 = mh * 48 + mi * 16 + (lane >> 2);
#pragma unroll
            for (int nb = 0; nb < 2; nb++) {
                const int c0 = nq * 16 + nb * 8 + 2 * (lane & 3);
                if (wm == 1) {
                    char* lb = smem + QL_OFF;
                    uint16_t h0, l0, h1, l1;
                    split(acc[j][mi][nb][0], h0, l0); split(acc[j][mi][nb][1], h1, l1);
                    *(uint32_t*)(hb + (r0 * KS + c0) * 2) = (uint32_t)h0 | ((uint32_t)h1 << 16);
                    *(uint32_t*)(lb + (r0 * KS + c0) * 2) = (uint32_t)l0 | ((uint32_t)l1 << 16);
                    split(acc[j][mi][nb][2], h0, l0); split(acc[j][mi][nb][3], h1, l1);
                    *(uint32_t*)(hb + ((r0 + 8) * KS + c0) * 2) = (uint32_t)h0 | ((uint32_t)h1 << 16);
                    *(uint32_t*)(lb + ((r0 + 8) * KS + c0) * 2) = (uint32_t)l0 | ((uint32_t)l1 << 16);
                } else {
                    *(uint32_t*)(hb + (r0 * KS + c0) * 2) =
                        pack2h(acc[j][mi][nb][0], acc[j][mi][nb][1]);
                    *(uint32_t*)(hb + ((r0 + 8) * KS + c0) * 2) =
                        pack2h(acc[j][mi][nb][2], acc[j][mi][nb][3]);
                }
            }
        }
    }
    __syncthreads();

    // ---------------- phase 2: S = q k^T, balanced units across 8 warps (R11 schedule) ----------------
    const uint64_t U0 = 0x28ULL | (0x2BULL << 6) | (0x20ULL << 12) | (0x23ULL << 18)
                      | (0x18ULL << 24) | (0x10ULL << 30) | (0x08ULL << 36);
    const uint64_t U1 = 0x29ULL | (0x2CULL << 6) | (0x21ULL << 12) | (0x24ULL << 18)
                      | (0x19ULL << 24) | (0x11ULL << 30) | (0x09ULL << 36);
    const uint64_t U2 = 0x2AULL | (0x2DULL << 6) | (0x22ULL << 12) | (0x1BULL << 18)
                      | (0x1AULL << 24) | (0x12ULL << 30);
    const uint32_t CNT2 = 0x12333333u;
    const int n2 = (CNT2 >> (4 * w)) & 15;
    const int u0 = (int)((U0 >> (6 * w)) & 63);
    const int u1 = (int)((U1 >> (6 * w)) & 63);
    const int u2 = (int)((U2 >> (6 * w)) & 63);

    float s[3][2][4];
#pragma unroll
    for (int u = 0; u < 3; u++)
#pragma unroll
        for (int nb = 0; nb < 2; nb++)
#pragma unroll
            for (int i = 0; i < 4; i++) s[u][nb][i] = 0.f;

#pragma unroll
    for (int u = 0; u < 3; u++) {
        if (u >= n2) break;
        const int unit = (u == 0) ? u0 : ((u == 1) ? u1 : u2);
        const int mt = unit >> 3, nb2 = unit & 7;
#pragma unroll
        for (int kit = 0; kit < 4; kit++) {
            const int k0 = kit * 16;
            unsigned qh[4], ql[4], kh[4];
            uint32_t ao = (uint32_t)((mt * 16 + (lane & 15)) * KS + k0 + 8 * (lane >> 4)) * 2u;
            ldsm_x4(qh, sb + QH_OFF + ao);
            ldsm_x4(ql, sb + QL_OFF + ao);
            uint32_t bo = (uint32_t)((nb2 * 16 + (lane & 7) + 8 * (lane >> 4)) * KS
                                     + k0 + 8 * ((lane >> 3) & 1)) * 2u;
            ldsm_x4(kh, sb + KH_OFF + bo);
            mma16816(s[u][0], qh, kh);
            mma16816(s[u][0], ql, kh);
            mma16816(s[u][1], qh, kh + 2);
            mma16816(s[u][1], ql, kh + 2);
        }
    }

    // partial row-max per unit -> SMAX[r][nb2]
    {
        float* SMX = (float*)(smem + SMAX_OFF);
#pragma unroll
        for (int u = 0; u < 3; u++) {
            if (u >= n2) break;
            const int unit = (u == 0) ? u0 : ((u == 1) ? u1 : u2);
            const int mt = unit >> 3, nb2 = unit & 7;
            const int r0 = mt * 16 + (lane >> 2), r1 = r0 + 8;
            const int cbase = nb2 * 16 + 2 * (lane & 3);
            const bool diag = (nb2 == mt);
            float m0 = -1e30f, m1 = -1e30f;
#pragma unroll
            for (int nb = 0; nb < 2; nb++) {
                int cc = cbase + nb * 8;
                if (!diag || cc     <= r0) m0 = fmaxf(m0, s[u][nb][0]);
                if (!diag || cc + 1 <= r0) m0 = fmaxf(m0, s[u][nb][1]);
                if (!diag || cc     <= r1) m1 = fmaxf(m1, s[u][nb][2]);
                if (!diag || cc + 1 <= r1) m1 = fmaxf(m1, s[u][nb][3]);
            }
            m0 = fmaxf(m0, __shfl_xor_sync(0xffffffffu, m0, 1));
            m0 = fmaxf(m0, __shfl_xor_sync(0xffffffffu, m0, 2));
            m1 = fmaxf(m1, __shfl_xor_sync(0xffffffffu, m1, 1));
            m1 = fmaxf(m1, __shfl_xor_sync(0xffffffffu, m1, 2));
            if ((lane & 3) == 0) {
                SMX[r0 * 9 + nb2] = m0;
                SMX[r1 * 9 + nb2] = m1;
            }
        }
    }
    __syncthreads();

    if (tid < T) {
        const float* SMX = (const float*)(smem + SMAX_OFF);
        float m = SMX[tid * 9];
        const int segs = tid >> 4;
#pragma unroll 1
        for (int sg = 1; sg <= segs; sg++) m = fmaxf(m, SMX[tid * 9 + sg]);
        ((float*)(smem + RMAX_OFF))[tid] = m;
    }
    __syncthreads();

    // exp + P write (hi only, unnormalized) + partial sums
    {
        const float* RMX = (const float*)(smem + RMAX_OFF);
        float* SMX = (float*)(smem + SMAX_OFF);
        uint16_t* PH = (uint16_t*)(smem + PH_OFF);
#pragma unroll
        for (int u = 0; u < 3; u++) {
            if (u >= n2) break;
            const int unit = (u == 0) ? u0 : ((u == 1) ? u1 : u2);
            const int mt = unit >> 3, nb2 = unit & 7;
            const int r0 = mt * 16 + (lane >> 2), r1 = r0 + 8;
            const int cbase = nb2 * 16 + 2 * (lane & 3);
            const bool diag = (nb2 == mt);
            const float rm0 = RMX[r0] * SCALE, rm1 = RMX[r1] * SCALE;
            float sum0 = 0.f, sum1 = 0.f;
#pragma unroll
            for (int nb = 0; nb < 2; nb++) {
                int cc = cbase + nb * 8;
                float p0 = (!diag || cc     <= r0) ? __expf(s[u][nb][0] * SCALE - rm0) : 0.f;
                float p1 = (!diag || cc + 1 <= r0) ? __expf(s[u][nb][1] * SCALE - rm0) : 0.f;
                float p2 = (!diag || cc     <= r1) ? __expf(s[u][nb][2] * SCALE - rm1) : 0.f;
                float p3 = (!diag || cc + 1 <= r1) ? __expf(s[u][nb][3] * SCALE - rm1) : 0.f;
                sum0 += p0 + p1; sum1 += p2 + p3;
                *(uint32_t*)&PH[r0 * PS + cc] = pack2h(p0, p1);
                *(uint32_t*)&PH[r1 * PS + cc] = pack2h(p2, p3);
            }
            sum0 += __shfl_xor_sync(0xffffffffu, sum0, 1);
            sum0 += __shfl_xor_sync(0xffffffffu, sum0, 2);
            sum1 += __shfl_xor_sync(0xffffffffu, sum1, 1);
            sum1 += __shfl_xor_sync(0xffffffffu, sum1, 2);
            if ((lane & 3) == 0) {
                SMX[r0 * 9 + nb2] = sum0;
                SMX[r1 * 9 + nb2] = sum1;
            }
        }
    }
    __syncthreads();

    if (tid < T) {
        const float* SMX = (const float*)(smem + SMAX_OFF);
        float sm = SMX[tid * 9];
        const int segs = tid >> 4;
#pragma unroll 1
        for (int sg = 1; sg <= segs; sg++) sm += SMX[tid * 9 + sg];
        ((float*)(smem + INV_OFF))[tid] = 1.f / sm;
    }
    __syncthreads();

    // ---------------- phase 3: O = P @ v, single-pass P, balanced (mt, nh) units ----------------
    const uint32_t V0 = 0x547698BAu, V1 = 0x10320000u, CNT3 = 0x22221111u;
    const int n3  = (CNT3 >> (4 * w)) & 15;
    const int vu0 = (V0 >> (4 * w)) & 15;
    const int vu1 = (V1 >> (4 * w)) & 15;
    const float* INV = (const float*)(smem + INV_OFF);
    float* ob = out + (size_t)b * T * H;

    float o[2][4][4];
#pragma unroll
    for (int u = 0; u < 2; u++)
#pragma unroll
        for (int nb = 0; nb < 4; nb++)
#pragma unroll
            for (int i = 0; i < 4; i++) o[u][nb][i] = 0.f;

#pragma unroll
    for (int u = 0; u < 2; u++) {
        if (u >= n3) break;
        const int unit = (u == 0) ? vu0 : vu1;
        const int pmt = unit >> 1, nh = unit & 1;
#pragma unroll 1
        for (int kit = 0; kit <= pmt; kit++) {
            const int k0 = kit * 16;
            unsigned ph[4], vh[4];
            uint32_t ao = (uint32_t)((pmt * 16 + (lane & 15)) * PS + k0 + 8 * (lane >> 4)) * 2u;
            ldsm_x4(ph, sb + PH_OFF + ao);
            uint32_t bo = (uint32_t)((k0 + (lane & 15)) * KS + nh * 32 + 16 * (lane >> 4)) * 2u;
            ldsm_x4t(vh, sb + VH_OFF + bo);
            mma16816(o[u][0], ph, vh);
            mma16816(o[u][2], ph, vh + 2);
            uint32_t bo2 = bo + 16u;
            ldsm_x4t(vh, sb + VH_OFF + bo2);
            mma16816(o[u][1], ph, vh);
            mma16816(o[u][3], ph, vh + 2);
        }
        const int r0 = pmt * 16 + (lane >> 2), r1 = r0 + 8;
        const float inv0 = INV[r0], inv1 = INV[r1];
#pragma unroll
        for (int nb = 0; nb < 4; nb++) {
            int cc = nh * 32 + nb * 8 + 2 * (lane & 3);
            *(float2*)&ob[r0 * H + cc] = make_float2(o[u][nb][0] * inv0, o[u][nb][1] * inv0);
            *(float2*)&ob[r1 * H + cc] = make_float2(o[u][nb][2] * inv1, o[u][nb][3] * inv1);
        }
    }
}

extern "C" void kernel_launch(void* const* d_in, const int* in_sizes, int n_in,
                              void* d_out, int out_size)
{
    const float* x  = (const float*)d_in[0];
    const float* Wk = (const float*)d_in[1];
    const float* Wq = (const float*)d_in[2];
    const float* Wv = (const float*)d_in[3];
    float* out = (float*)d_out;

    static bool attr_set = false;
    if (!attr_set) {
        cudaFuncSetAttribute(head_attn_v10,
                             cudaFuncAttributeMaxDynamicSharedMemorySize, SMEM_BYTES);
        attr_set = true;
    }
    convW_kernel<<<192, 256>>>(Wk, Wq, Wv);
    head_attn_v10<<<BATCH, NT, SMEM_BYTES>>>(x, out);
}